// round 1
// baseline (speedup 1.0000x reference)
#include <cuda_runtime.h>

#define KCODES 512
#define DIM 64
#define CHUNK 128          // codes per smem chunk (32 KB)
#define THREADS 512
#define NPIX (64 * 1024)   // 65536 pixels total
#define HW 1024            // h*w stride between d-planes

typedef unsigned long long u64;

__device__ float g_e2[KCODES];

// ---- packed f32x2 helpers (Blackwell-only, PTX required) ----
__device__ __forceinline__ u64 pk2(float lo, float hi) {
    u64 r;
    asm("mov.b64 %0, {%1, %2};" : "=l"(r) : "f"(lo), "f"(hi));
    return r;
}
__device__ __forceinline__ void upk2(u64 v, float& lo, float& hi) {
    asm("mov.b64 {%0, %1}, %2;" : "=f"(lo), "=f"(hi) : "l"(v));
}
__device__ __forceinline__ void fma2(u64& d, u64 a, u64 b) {
    asm("fma.rn.f32x2 %0, %1, %2, %0;" : "+l"(d) : "l"(a), "l"(b));
}
__device__ __forceinline__ u64 add2(u64 a, u64 b) {
    u64 r;
    asm("add.rn.f32x2 %0, %1, %2;" : "=l"(r) : "l"(a), "l"(b));
    return r;
}

// Precompute ||e_k||^2 for each code.
__global__ void e2_kernel(const float* __restrict__ cb) {
    int k = blockIdx.x * blockDim.x + threadIdx.x;
    if (k < KCODES) {
        float s = 0.f;
#pragma unroll
        for (int d = 0; d < DIM; d++) {
            float v = cb[k * DIM + d];
            s = fmaf(v, v, s);
        }
        g_e2[k] = s;
    }
}

__global__ __launch_bounds__(THREADS, 1)
void vq_kernel(const float* __restrict__ x, const float* __restrict__ cb,
               float* __restrict__ out) {
    __shared__ float4 s_cb[CHUNK * DIM / 4];  // 32 KB
    __shared__ float  s_e2[CHUNK];

    const int tid = threadIdx.x;
    const int p   = blockIdx.x * THREADS + tid;   // global pixel id
    const int b   = p >> 10;                      // batch
    const int nl  = p & (HW - 1);                 // pixel within image

    const float* xb = x + (size_t)b * DIM * HW + nl;

    // Load this pixel's 64-dim vector into 32 packed f32x2 registers.
    // Per-d loads are coalesced across the warp (consecutive nl).
    u64 xv[DIM / 2];
#pragma unroll
    for (int j = 0; j < DIM / 2; j++) {
        float lo = xb[(2 * j) * HW];
        float hi = xb[(2 * j + 1) * HW];
        xv[j] = pk2(lo, hi);
    }

    float best  = __int_as_float(0x7f800000);  // +inf
    int   bestk = 0;

    for (int c0 = 0; c0 < KCODES; c0 += CHUNK) {
        __syncthreads();  // previous chunk fully consumed
        // Cooperative chunk load: 2048 float4 by 512 threads (4 each)
        const float4* src = reinterpret_cast<const float4*>(cb + c0 * DIM);
#pragma unroll
        for (int i = 0; i < (CHUNK * DIM / 4) / THREADS; i++)
            s_cb[i * THREADS + tid] = src[i * THREADS + tid];
        if (tid < CHUNK) s_e2[tid] = g_e2[c0 + tid];
        __syncthreads();

        for (int k = 0; k < CHUNK; k++) {
            const float4* cp = &s_cb[k * (DIM / 4)];
            u64 a0 = 0, a1 = 0, a2 = 0, a3 = 0;
#pragma unroll
            for (int j = 0; j < DIM / 4; j += 2) {
                float4 q0 = cp[j];       // broadcast LDS.128
                float4 q1 = cp[j + 1];
                fma2(a0, xv[2 * j],     pk2(q0.x, q0.y));
                fma2(a1, xv[2 * j + 1], pk2(q0.z, q0.w));
                fma2(a2, xv[2 * j + 2], pk2(q1.x, q1.y));
                fma2(a3, xv[2 * j + 3], pk2(q1.z, q1.w));
            }
            u64 a = add2(add2(a0, a1), add2(a2, a3));
            float lo, hi;
            upk2(a, lo, hi);
            float dot   = lo + hi;
            float score = fmaf(-2.f, dot, s_e2[k]);  // ||e||^2 - 2 x.e
            if (score < best) { best = score; bestk = c0 + k; }
        }
    }

    // Gather winning code (codebook is L2-hot) and scatter to (b, d, h, w).
    const float4* code = reinterpret_cast<const float4*>(cb + bestk * DIM);
    float* ob = out + (size_t)b * DIM * HW + nl;
#pragma unroll
    for (int j = 0; j < DIM / 4; j++) {
        float4 q = code[j];
        ob[(4 * j + 0) * HW] = q.x;
        ob[(4 * j + 1) * HW] = q.y;
        ob[(4 * j + 2) * HW] = q.z;
        ob[(4 * j + 3) * HW] = q.w;
    }
}

extern "C" void kernel_launch(void* const* d_in, const int* in_sizes, int n_in,
                              void* d_out, int out_size) {
    const float* x  = (const float*)d_in[0];   // (64, 64, 32, 32) fp32
    const float* cb = (const float*)d_in[1];   // (512, 64) fp32
    float* out = (float*)d_out;

    e2_kernel<<<1, KCODES>>>(cb);
    vq_kernel<<<NPIX / THREADS, THREADS>>>(x, cb, out);
}

// round 2
// speedup vs baseline: 1.1416x; 1.1416x over previous
#include <cuda_runtime.h>

#define KCODES 512
#define DIM 64
#define TILE_P 128         // pixels per CTA
#define KC 128             // codes per smem chunk
#define THREADS 256
#define NPIX 65536
#define HW 1024

typedef unsigned long long u64;

__device__ float g_e2[KCODES];
__device__ float g_cbT[DIM * KCODES];   // transposed codebook [d][k]

// ---- packed f32x2 helpers (Blackwell, PTX-only) ----
__device__ __forceinline__ u64 pk2(float lo, float hi) {
    u64 r;
    asm("mov.b64 %0, {%1, %2};" : "=l"(r) : "f"(lo), "f"(hi));
    return r;
}
__device__ __forceinline__ void upk2(u64 v, float& lo, float& hi) {
    asm("mov.b64 {%0, %1}, %2;" : "=f"(lo), "=f"(hi) : "l"(v));
}
__device__ __forceinline__ void fma2(u64& d, u64 a, u64 b) {
    asm("fma.rn.f32x2 %0, %1, %2, %0;" : "+l"(d) : "l"(a), "l"(b));
}

// Precompute e2[k] = ||code_k||^2 and transposed codebook cbT[d][k].
__global__ void prep_kernel(const float* __restrict__ cb) {
    int k = threadIdx.x;   // 512 threads
    float s = 0.f;
#pragma unroll
    for (int d = 0; d < DIM; d++) {
        float v = cb[k * DIM + d];
        g_cbT[d * KCODES + k] = v;
        s = fmaf(v, v, s);
    }
    g_e2[k] = s;
}

extern __shared__ float smem[];
// layout (floats): sx[64][128] @0 (8192), scb[64][128] @8192 (8192), se2[128] @16384
// after compute, sx region reused: rsc[16][128] @0, rid[16][128] @2048, sbk[128] @4096

__global__ __launch_bounds__(THREADS, 1)
void vq_kernel(const float* __restrict__ x, const float* __restrict__ cb,
               float* __restrict__ out) {
    float* sx  = smem;
    float* scb = smem + 8192;
    float* se2 = smem + 16384;

    const int tid = threadIdx.x;
    const int tp  = tid & 15;    // pixel-group 0..15 (8 pixels each)
    const int tk  = tid >> 4;    // code-group  0..15 (8 codes each)

    const int P   = blockIdx.x * TILE_P;   // global pixel base
    const int b   = P >> 10;
    const int nl0 = P & (HW - 1);

    // ---- stage x tile: sx[d][p], coalesced float4 loads ----
    const float4* x4  = reinterpret_cast<const float4*>(x + (size_t)b * DIM * HW + nl0);
    float4*       sx4 = reinterpret_cast<float4*>(sx);
#pragma unroll
    for (int t = 0; t < 8; t++) {
        int idx = t * THREADS + tid;       // 0..2047
        int d = idx >> 5, c = idx & 31;
        sx4[d * 32 + c] = x4[d * 256 + c]; // x row stride = 1024 floats = 256 float4
    }

    float best[8];
    int   bidx[8];
#pragma unroll
    for (int i = 0; i < 8; i++) { best[i] = 3.4e38f; bidx[i] = 0; }

    const float4* cbT4 = reinterpret_cast<const float4*>(g_cbT);  // row = 128 float4

    for (int c0 = 0; c0 < KCODES; c0 += KC) {
        __syncthreads();
        // stage code chunk: scb[d][k] = cbT[d][c0+k]
        float4* scb4 = reinterpret_cast<float4*>(scb);
        const int cb0 = c0 >> 2;
#pragma unroll
        for (int t = 0; t < 8; t++) {
            int idx = t * THREADS + tid;
            int d = idx >> 5, c = idx & 31;
            scb4[d * 32 + c] = cbT4[d * 128 + cb0 + c];
        }
        if (tid < KC) se2[tid] = g_e2[c0 + tid];
        __syncthreads();

        u64 acc[4][8];
#pragma unroll
        for (int i = 0; i < 4; i++)
#pragma unroll
            for (int j = 0; j < 8; j++) acc[i][j] = 0ull;

#pragma unroll 8
        for (int d = 0; d < DIM; d++) {
            const ulonglong2* xr =
                reinterpret_cast<const ulonglong2*>(sx + d * TILE_P + tp * 8);
            ulonglong2 xa = xr[0];   // pairs (p0,p1),(p2,p3)
            ulonglong2 xb = xr[1];   // pairs (p4,p5),(p6,p7)

            const float4* cr =
                reinterpret_cast<const float4*>(scb + d * KC + tk * 8);
            float4 cA = cr[0];
            float4 cB = cr[1];

            u64 k0 = pk2(cA.x, cA.x), k1 = pk2(cA.y, cA.y);
            u64 k2 = pk2(cA.z, cA.z), k3 = pk2(cA.w, cA.w);
            u64 k4 = pk2(cB.x, cB.x), k5 = pk2(cB.y, cB.y);
            u64 k6 = pk2(cB.z, cB.z), k7 = pk2(cB.w, cB.w);

            fma2(acc[0][0], xa.x, k0); fma2(acc[1][0], xa.y, k0);
            fma2(acc[2][0], xb.x, k0); fma2(acc[3][0], xb.y, k0);
            fma2(acc[0][1], xa.x, k1); fma2(acc[1][1], xa.y, k1);
            fma2(acc[2][1], xb.x, k1); fma2(acc[3][1], xb.y, k1);
            fma2(acc[0][2], xa.x, k2); fma2(acc[1][2], xa.y, k2);
            fma2(acc[2][2], xb.x, k2); fma2(acc[3][2], xb.y, k2);
            fma2(acc[0][3], xa.x, k3); fma2(acc[1][3], xa.y, k3);
            fma2(acc[2][3], xb.x, k3); fma2(acc[3][3], xb.y, k3);
            fma2(acc[0][4], xa.x, k4); fma2(acc[1][4], xa.y, k4);
            fma2(acc[2][4], xb.x, k4); fma2(acc[3][4], xb.y, k4);
            fma2(acc[0][5], xa.x, k5); fma2(acc[1][5], xa.y, k5);
            fma2(acc[2][5], xb.x, k5); fma2(acc[3][5], xb.y, k5);
            fma2(acc[0][6], xa.x, k6); fma2(acc[1][6], xa.y, k6);
            fma2(acc[2][6], xb.x, k6); fma2(acc[3][6], xb.y, k6);
            fma2(acc[0][7], xa.x, k7); fma2(acc[1][7], xa.y, k7);
            fma2(acc[2][7], xb.x, k7); fma2(acc[3][7], xb.y, k7);
        }

        // score this chunk: dist = e2[k] - 2*dot  (x^2 term constant per pixel)
#pragma unroll
        for (int j = 0; j < 8; j++) {
            float e2v = se2[tk * 8 + j];
            int   kk  = c0 + tk * 8 + j;
#pragma unroll
            for (int i = 0; i < 4; i++) {
                float lo, hi;
                upk2(acc[i][j], lo, hi);
                float s0 = fmaf(-2.f, lo, e2v);
                float s1 = fmaf(-2.f, hi, e2v);
                if (s0 < best[2 * i])     { best[2 * i]     = s0; bidx[2 * i]     = kk; }
                if (s1 < best[2 * i + 1]) { best[2 * i + 1] = s1; bidx[2 * i + 1] = kk; }
            }
        }
    }

    // ---- cross-thread reduction over tk (16 candidates per pixel) ----
    __syncthreads();                         // done reading sx; reuse it
    float* rsc = smem;                       // [16][128]
    int*   rid = reinterpret_cast<int*>(smem + 2048);
    int*   sbk = reinterpret_cast<int*>(smem + 4096);
#pragma unroll
    for (int i = 0; i < 8; i++) {
        rsc[tk * TILE_P + tp * 8 + i] = best[i];
        rid[tk * TILE_P + tp * 8 + i] = bidx[i];
    }
    __syncthreads();
    if (tid < TILE_P) {
        float bs = rsc[tid];
        int   bk = rid[tid];
#pragma unroll
        for (int t = 1; t < 16; t++) {
            float v = rsc[t * TILE_P + tid];
            if (v < bs) { bs = v; bk = rid[t * TILE_P + tid]; }
        }
        sbk[tid] = bk;
    }
    __syncthreads();

    // ---- gather winning codes, write (b, d, h, w); coalesced stores ----
    float* ob = out + (size_t)b * DIM * HW + nl0;
#pragma unroll
    for (int t = 0; t < 32; t++) {
        int idx = t * THREADS + tid;   // 0..8191
        int d = idx >> 7, p = idx & 127;
        ob[d * HW + p] = cb[sbk[p] * DIM + d];
    }
}

extern "C" void kernel_launch(void* const* d_in, const int* in_sizes, int n_in,
                              void* d_out, int out_size) {
    const float* x  = (const float*)d_in[0];   // (64, 64, 32, 32) fp32
    const float* cb = (const float*)d_in[1];   // (512, 64) fp32
    float* out = (float*)d_out;

    static const int smem_bytes = (8192 + 8192 + 128) * 4;  // 66048
    cudaFuncSetAttribute(vq_kernel, cudaFuncAttributeMaxDynamicSharedMemorySize,
                         smem_bytes);

    prep_kernel<<<1, KCODES>>>(cb);
    vq_kernel<<<NPIX / TILE_P, THREADS, smem_bytes>>>(x, cb, out);
}

// round 4
// speedup vs baseline: 2.5688x; 2.2501x over previous
#include <cuda_runtime.h>
#include <cuda_fp16.h>
#include <cstdint>

#define NPIX    65536
#define HW      1024
#define DIM     64
#define KCODES  512
#define NHALF   256          // codes per CTA
#define TILE_M  128          // pixels per tile
#define NTILES  512
#define NSLOTS  148
#define GRID    (2 * NSLOTS)
#define THREADS 256

// smem byte offsets; rows padded to 144B (72 halves) -> conflict-free ldmatrix
#define ROWB    144
#define OFF_AHI 0
#define OFF_ALO (OFF_AHI + TILE_M * ROWB)   // 18432
#define OFF_BHI (OFF_ALO + TILE_M * ROWB)   // 36864
#define OFF_BLO (OFF_BHI + NHALF * ROWB)    // 73728
#define OFF_E2  (OFF_BLO + NHALF * ROWB)    // 110592
#define SMEM_SZ (OFF_E2 + NHALF * 4)        // 111616

__device__ float g_e2h[KCODES];     // 0.5 * ||e_k||^2
__device__ float g_best[2 * NPIX];
__device__ int   g_bidx[2 * NPIX];

static __device__ __forceinline__ uint32_t s2u(const void* p) {
    uint32_t a;
    asm("{ .reg .u64 t; cvta.to.shared.u64 t, %1; cvt.u32.u64 %0, t; }"
        : "=r"(a) : "l"(p));
    return a;
}

#define LDSM_X4(r, addr) \
    asm volatile("ldmatrix.sync.aligned.m8n8.x4.shared.b16 {%0,%1,%2,%3}, [%4];" \
        : "=r"((r)[0]), "=r"((r)[1]), "=r"((r)[2]), "=r"((r)[3]) : "r"(addr))

static __device__ __forceinline__ void mma16816(float* d, const uint32_t* a,
                                                const uint32_t* b) {
    asm volatile(
        "mma.sync.aligned.m16n8k16.row.col.f32.f16.f16.f32 "
        "{%0,%1,%2,%3}, {%4,%5,%6,%7}, {%8,%9}, {%0,%1,%2,%3};"
        : "+f"(d[0]), "+f"(d[1]), "+f"(d[2]), "+f"(d[3])
        : "r"(a[0]), "r"(a[1]), "r"(a[2]), "r"(a[3]), "r"(b[0]), "r"(b[1]));
}

__global__ void prep_kernel(const float* __restrict__ cb) {
    int k = threadIdx.x;
    float s = 0.f;
#pragma unroll
    for (int d = 0; d < DIM; d++) {
        float v = cb[k * DIM + d];
        s = fmaf(v, v, s);
    }
    g_e2h[k] = 0.5f * s;
}

__global__ void __launch_bounds__(THREADS, 2)
vq_main(const float* __restrict__ x, const float* __restrict__ cb) {
    extern __shared__ char smem[];
    const uint32_t sb = s2u(smem);
    const int tid  = threadIdx.x;
    const int wid  = tid >> 5, lane = tid & 31;

    const int half  = blockIdx.x & 1;
    const int slot  = blockIdx.x >> 1;
    const int kbase = half * NHALF;

    // ---- stage B half (256 codes) as fp16 hi/lo, padded rows ----
    {
        const float4* cb4 = reinterpret_cast<const float4*>(cb + kbase * DIM);
#pragma unroll
        for (int i = 0; i < (NHALF * DIM / 4) / THREADS; i++) {   // 16 iters
            int idx = i * THREADS + tid;          // 0..4095
            int kr = idx >> 4, d4 = idx & 15;
            float4 v = cb4[idx];
            __half hh[4], ll[4];
            hh[0] = __float2half_rn(v.x); ll[0] = __float2half_rn(v.x - __half2float(hh[0]));
            hh[1] = __float2half_rn(v.y); ll[1] = __float2half_rn(v.y - __half2float(hh[1]));
            hh[2] = __float2half_rn(v.z); ll[2] = __float2half_rn(v.z - __half2float(hh[2]));
            hh[3] = __float2half_rn(v.w); ll[3] = __float2half_rn(v.w - __half2float(hh[3]));
            uint32_t off = kr * ROWB + d4 * 8;
            *(uint2*)(smem + OFF_BHI + off) = *(const uint2*)hh;
            *(uint2*)(smem + OFF_BLO + off) = *(const uint2*)ll;
        }
        if (tid < NHALF) ((float*)(smem + OFF_E2))[tid] = g_e2h[kbase + tid];
    }
    __syncthreads();

    const float* se2 = (const float*)(smem + OFF_E2);
    const int R0 = wid * 16;   // warp's pixel-row base within tile

    for (int t = slot; t < NTILES; t += NSLOTS) {
        const int P0  = t * TILE_M;
        const int b   = P0 >> 10;
        const int nl0 = P0 & (HW - 1);
        const float* src = x + (size_t)b * DIM * HW + nl0;

        // ---- stage A tile (128 px x 64 d) fp16 hi/lo, [pixel][dim] ----
        {
            const int row = tid & 127;
            const int d0  = (tid >> 7) * 32;
#pragma unroll
            for (int blk = 0; blk < 4; blk++) {
                __half hh[8], ll[8];
#pragma unroll
                for (int j = 0; j < 8; j++) {
                    float v = src[(size_t)(d0 + blk * 8 + j) * HW + row];
                    hh[j] = __float2half_rn(v);
                    ll[j] = __float2half_rn(v - __half2float(hh[j]));
                }
                uint32_t off = row * ROWB + (d0 + blk * 8) * 2;
                *(uint4*)(smem + OFF_AHI + off) = *(const uint4*)hh;
                *(uint4*)(smem + OFF_ALO + off) = *(const uint4*)ll;
            }
        }
        __syncthreads();

        float best0 = 3.4e38f, best1 = 3.4e38f;
        int   bi0 = 0, bi1 = 0;

        // A ldmatrix address: lane -> row R0+(lane&15), col-half (lane>>4)
        const uint32_t aoff = (R0 + (lane & 15)) * ROWB + (lane >> 4) * 16;
        // B ldmatrix address: lane -> code row (lane&7), 16B chunk (lane>>3)
        const uint32_t boff_lane = (lane & 7) * ROWB + (lane >> 3) * 16;

#pragma unroll
        for (int c0 = 0; c0 < NHALF; c0 += 64) {      // 4 chunks of 64 codes
            float acc[8][4];
#pragma unroll
            for (int nt = 0; nt < 8; nt++)
#pragma unroll
                for (int j = 0; j < 4; j++) acc[nt][j] = 0.f;

#pragma unroll
            for (int kp = 0; kp < 2; kp++) {          // pairs of k-steps
                uint32_t ah[2][4], al[2][4];
#pragma unroll
                for (int ks = 0; ks < 2; ks++) {
                    uint32_t q = (kp * 2 + ks) * 32;  // 16 dims = 32B
                    LDSM_X4(ah[ks], sb + OFF_AHI + aoff + q);
                    LDSM_X4(al[ks], sb + OFF_ALO + aoff + q);
                }
#pragma unroll
                for (int nt = 0; nt < 8; nt++) {
                    uint32_t bb = (c0 + nt * 8) * ROWB + kp * 64 + boff_lane;
                    uint32_t bh[4], bl[4];
                    LDSM_X4(bh, sb + OFF_BHI + bb);
                    LDSM_X4(bl, sb + OFF_BLO + bb);
                    mma16816(acc[nt], ah[0], bh + 0);
                    mma16816(acc[nt], ah[1], bh + 2);
                    mma16816(acc[nt], ah[0], bl + 0);
                    mma16816(acc[nt], ah[1], bl + 2);
                    mma16816(acc[nt], al[0], bh + 0);
                    mma16816(acc[nt], al[1], bh + 2);
                }
            }

            // score: dist/2 = 0.5*||e||^2 - dot ; rows r0=(lane>>2), r1=r0+8
#pragma unroll
            for (int nt = 0; nt < 8; nt++) {
                int cbase = c0 + nt * 8 + (lane & 3) * 2;
#pragma unroll
                for (int j = 0; j < 2; j++) {
                    float e = se2[cbase + j];
                    int   c = cbase + j;
                    float s0 = e - acc[nt][j];
                    float s1 = e - acc[nt][2 + j];
                    if (s0 < best0) { best0 = s0; bi0 = c; }
                    if (s1 < best1) { best1 = s1; bi1 = c; }
                }
            }
        }

        // reduce across the 4 lanes sharing each row (lane&3 groups)
#pragma unroll
        for (int m = 1; m <= 2; m <<= 1) {
            float o0 = __shfl_xor_sync(0xffffffffu, best0, m);
            int   i0 = __shfl_xor_sync(0xffffffffu, bi0, m);
            float o1 = __shfl_xor_sync(0xffffffffu, best1, m);
            int   i1 = __shfl_xor_sync(0xffffffffu, bi1, m);
            if (o0 < best0 || (o0 == best0 && i0 < bi0)) { best0 = o0; bi0 = i0; }
            if (o1 < best1 || (o1 == best1 && i1 < bi1)) { best1 = o1; bi1 = i1; }
        }
        if ((lane & 3) == 0) {
            int gp = P0 + R0 + (lane >> 2);
            g_best[half * NPIX + gp]     = best0;
            g_bidx[half * NPIX + gp]     = kbase + bi0;
            g_best[half * NPIX + gp + 8] = best1;
            g_bidx[half * NPIX + gp + 8] = kbase + bi1;
        }
        __syncthreads();   // A buffer reusable
    }
}

// ---------------- combine halves + gather + transpose-write ----------------
__global__ void __launch_bounds__(256)
combine_kernel(const float* __restrict__ cb, float* __restrict__ out) {
    const int tid = threadIdx.x;
    const int P0  = blockIdx.x * 256;
    const int p   = P0 + tid;

    float b0 = g_best[p], b1 = g_best[NPIX + p];
    int k = (b0 <= b1) ? g_bidx[p] : g_bidx[NPIX + p];

    const int b   = P0 >> 10;
    const int nl0 = P0 & (HW - 1);
    float* ob = out + (size_t)b * DIM * HW + nl0;

    const float4* crow = (const float4*)(cb + k * DIM);
#pragma unroll
    for (int j = 0; j < DIM / 4; j++) {
        float4 v = crow[j];
        ob[(size_t)(4 * j + 0) * HW + tid] = v.x;
        ob[(size_t)(4 * j + 1) * HW + tid] = v.y;
        ob[(size_t)(4 * j + 2) * HW + tid] = v.z;
        ob[(size_t)(4 * j + 3) * HW + tid] = v.w;
    }
}

extern "C" void kernel_launch(void* const* d_in, const int* in_sizes, int n_in,
                              void* d_out, int out_size) {
    const float* x  = (const float*)d_in[0];   // (64, 64, 32, 32) fp32
    const float* cb = (const float*)d_in[1];   // (512, 64) fp32
    float* out = (float*)d_out;

    cudaFuncSetAttribute(vq_main, cudaFuncAttributeMaxDynamicSharedMemorySize,
                         SMEM_SZ);

    prep_kernel<<<1, KCODES>>>(cb);
    vq_main<<<GRID, THREADS, SMEM_SZ>>>(x, cb);
    combine_kernel<<<NPIX / 256, 256>>>(cb, out);
}

// round 5
// speedup vs baseline: 3.1639x; 1.2317x over previous
#include <cuda_runtime.h>
#include <cuda_fp16.h>
#include <cstdint>

#define NPIX    65536
#define HW      1024
#define DIM     64
#define KCODES  512
#define NHALF   256          // codes per CTA
#define TILE_M  128          // pixels per tile
#define NTILES  512
#define NSLOTS  148
#define GRID    (2 * NSLOTS)
#define THREADS 256

// smem byte offsets; rows padded to 144B (72 halves) -> conflict-free ldmatrix
#define ROWB    144
#define OFF_AHI 0
#define OFF_ALO (OFF_AHI + TILE_M * ROWB)   // 18432
#define OFF_BHI (OFF_ALO + TILE_M * ROWB)   // 36864
#define OFF_BLO (OFF_BHI + NHALF * ROWB)    // 73728
#define OFF_E2  (OFF_BLO + NHALF * ROWB)    // 110592
#define SMEM_SZ (OFF_E2 + NHALF * 4)        // 111616

__device__ float g_best[2 * NPIX];
__device__ int   g_bidx[2 * NPIX];

static __device__ __forceinline__ uint32_t s2u(const void* p) {
    uint32_t a;
    asm("{ .reg .u64 t; cvta.to.shared.u64 t, %1; cvt.u32.u64 %0, t; }"
        : "=r"(a) : "l"(p));
    return a;
}

#define LDSM_X4(r, addr) \
    asm volatile("ldmatrix.sync.aligned.m8n8.x4.shared.b16 {%0,%1,%2,%3}, [%4];" \
        : "=r"((r)[0]), "=r"((r)[1]), "=r"((r)[2]), "=r"((r)[3]) : "r"(addr))

static __device__ __forceinline__ void mma16816(float* d, const uint32_t* a,
                                                const uint32_t* b) {
    asm volatile(
        "mma.sync.aligned.m16n8k16.row.col.f32.f16.f16.f32 "
        "{%0,%1,%2,%3}, {%4,%5,%6,%7}, {%8,%9}, {%0,%1,%2,%3};"
        : "+f"(d[0]), "+f"(d[1]), "+f"(d[2]), "+f"(d[3])
        : "r"(a[0]), "r"(a[1]), "r"(a[2]), "r"(a[3]), "r"(b[0]), "r"(b[1]));
}

__global__ void __launch_bounds__(THREADS, 2)
vq_main(const float* __restrict__ x, const float* __restrict__ cb) {
    extern __shared__ char smem[];
    const uint32_t sb = s2u(smem);
    const int tid  = threadIdx.x;
    const int wid  = tid >> 5, lane = tid & 31;

    const int half  = blockIdx.x & 1;
    const int slot  = blockIdx.x >> 1;
    const int kbase = half * NHALF;

    // ---- stage B half (256 codes) as fp16 hi/lo, padded rows ----
    {
        const float4* cb4 = reinterpret_cast<const float4*>(cb + kbase * DIM);
#pragma unroll
        for (int i = 0; i < (NHALF * DIM / 4) / THREADS; i++) {   // 16 iters
            int idx = i * THREADS + tid;          // 0..4095
            int kr = idx >> 4, d4 = idx & 15;
            float4 v = cb4[idx];
            __half hh[4], ll[4];
            hh[0] = __float2half_rn(v.x); ll[0] = __float2half_rn(v.x - __half2float(hh[0]));
            hh[1] = __float2half_rn(v.y); ll[1] = __float2half_rn(v.y - __half2float(hh[1]));
            hh[2] = __float2half_rn(v.z); ll[2] = __float2half_rn(v.z - __half2float(hh[2]));
            hh[3] = __float2half_rn(v.w); ll[3] = __float2half_rn(v.w - __half2float(hh[3]));
            uint32_t off = kr * ROWB + d4 * 8;
            *(uint2*)(smem + OFF_BHI + off) = *(const uint2*)hh;
            *(uint2*)(smem + OFF_BLO + off) = *(const uint2*)ll;
        }
        // inline e2: thread k computes 0.5*||code_{kbase+k}||^2 (L2-hot re-read)
        const float4* row = reinterpret_cast<const float4*>(cb + (kbase + tid) * DIM);
        float s = 0.f;
#pragma unroll
        for (int j = 0; j < DIM / 4; j++) {
            float4 v = row[j];
            s = fmaf(v.x, v.x, s);
            s = fmaf(v.y, v.y, s);
            s = fmaf(v.z, v.z, s);
            s = fmaf(v.w, v.w, s);
        }
        ((float*)(smem + OFF_E2))[tid] = 0.5f * s;
    }
    __syncthreads();

    const float* se2 = (const float*)(smem + OFF_E2);
    const int R0 = wid * 16;   // warp's pixel-row base within tile

    for (int t = slot; t < NTILES; t += NSLOTS) {
        const int P0  = t * TILE_M;
        const int b   = P0 >> 10;
        const int nl0 = P0 & (HW - 1);
        const float* src = x + (size_t)b * DIM * HW + nl0;

        // ---- stage A tile (128 px x 64 d) fp16 hi/lo, [pixel][dim] ----
        {
            const int row = tid & 127;
            const int d0  = (tid >> 7) * 32;
#pragma unroll
            for (int blk = 0; blk < 4; blk++) {
                __half hh[8], ll[8];
#pragma unroll
                for (int j = 0; j < 8; j++) {
                    float v = src[(size_t)(d0 + blk * 8 + j) * HW + row];
                    hh[j] = __float2half_rn(v);
                    ll[j] = __float2half_rn(v - __half2float(hh[j]));
                }
                uint32_t off = row * ROWB + (d0 + blk * 8) * 2;
                *(uint4*)(smem + OFF_AHI + off) = *(const uint4*)hh;
                *(uint4*)(smem + OFF_ALO + off) = *(const uint4*)ll;
            }
        }
        __syncthreads();

        float best0 = 3.4e38f, best1 = 3.4e38f;
        int   bi0 = 0, bi1 = 0;

        // A ldmatrix address: lane -> row R0+(lane&15), col-half (lane>>4)
        const uint32_t aoff = (R0 + (lane & 15)) * ROWB + (lane >> 4) * 16;
        // B ldmatrix address: lane -> code row (lane&7), 16B chunk (lane>>3)
        const uint32_t boff_lane = (lane & 7) * ROWB + (lane >> 3) * 16;

#pragma unroll
        for (int c0 = 0; c0 < NHALF; c0 += 64) {      // 4 chunks of 64 codes
            float acc[8][4];
#pragma unroll
            for (int nt = 0; nt < 8; nt++)
#pragma unroll
                for (int j = 0; j < 4; j++) acc[nt][j] = 0.f;

#pragma unroll
            for (int kp = 0; kp < 2; kp++) {          // pairs of k-steps
                uint32_t ah[2][4], al[2][4];
#pragma unroll
                for (int ks = 0; ks < 2; ks++) {
                    uint32_t q = (kp * 2 + ks) * 32;  // 16 dims = 32B
                    LDSM_X4(ah[ks], sb + OFF_AHI + aoff + q);
                    LDSM_X4(al[ks], sb + OFF_ALO + aoff + q);
                }
#pragma unroll
                for (int nt = 0; nt < 8; nt++) {
                    uint32_t bb = (c0 + nt * 8) * ROWB + kp * 64 + boff_lane;
                    uint32_t bh[4], bl[4];
                    LDSM_X4(bh, sb + OFF_BHI + bb);
                    LDSM_X4(bl, sb + OFF_BLO + bb);
                    mma16816(acc[nt], ah[0], bh + 0);
                    mma16816(acc[nt], ah[1], bh + 2);
                    mma16816(acc[nt], ah[0], bl + 0);
                    mma16816(acc[nt], ah[1], bl + 2);
                    mma16816(acc[nt], al[0], bh + 0);
                    mma16816(acc[nt], al[1], bh + 2);
                }
            }

            // score: dist/2 = 0.5*||e||^2 - dot ; rows r0=(lane>>2), r1=r0+8
#pragma unroll
            for (int nt = 0; nt < 8; nt++) {
                int cbase = c0 + nt * 8 + (lane & 3) * 2;
#pragma unroll
                for (int j = 0; j < 2; j++) {
                    float e = se2[cbase + j];
                    int   c = cbase + j;
                    float s0 = e - acc[nt][j];
                    float s1 = e - acc[nt][2 + j];
                    if (s0 < best0) { best0 = s0; bi0 = c; }
                    if (s1 < best1) { best1 = s1; bi1 = c; }
                }
            }
        }

        // reduce across the 4 lanes sharing each row (lane&3 groups)
#pragma unroll
        for (int m = 1; m <= 2; m <<= 1) {
            float o0 = __shfl_xor_sync(0xffffffffu, best0, m);
            int   i0 = __shfl_xor_sync(0xffffffffu, bi0, m);
            float o1 = __shfl_xor_sync(0xffffffffu, best1, m);
            int   i1 = __shfl_xor_sync(0xffffffffu, bi1, m);
            if (o0 < best0 || (o0 == best0 && i0 < bi0)) { best0 = o0; bi0 = i0; }
            if (o1 < best1 || (o1 == best1 && i1 < bi1)) { best1 = o1; bi1 = i1; }
        }
        if ((lane & 3) == 0) {
            int gp = P0 + R0 + (lane >> 2);
            g_best[half * NPIX + gp]     = best0;
            g_bidx[half * NPIX + gp]     = kbase + bi0;
            g_best[half * NPIX + gp + 8] = best1;
            g_bidx[half * NPIX + gp + 8] = kbase + bi1;
        }
        __syncthreads();   // A buffer reusable
    }
}

// ---------------- combine halves + gather + transpose-write ----------------
__global__ void __launch_bounds__(256)
combine_kernel(const float* __restrict__ cb, float* __restrict__ out) {
    const int tid = threadIdx.x;
    const int P0  = blockIdx.x * 256;
    const int p   = P0 + tid;

    float b0 = g_best[p], b1 = g_best[NPIX + p];
    int k = (b0 <= b1) ? g_bidx[p] : g_bidx[NPIX + p];

    const int b   = P0 >> 10;
    const int nl0 = P0 & (HW - 1);
    float* ob = out + (size_t)b * DIM * HW + nl0;

    const float4* crow = (const float4*)(cb + k * DIM);
#pragma unroll
    for (int j = 0; j < DIM / 4; j++) {
        float4 v = crow[j];
        ob[(size_t)(4 * j + 0) * HW + tid] = v.x;
        ob[(size_t)(4 * j + 1) * HW + tid] = v.y;
        ob[(size_t)(4 * j + 2) * HW + tid] = v.z;
        ob[(size_t)(4 * j + 3) * HW + tid] = v.w;
    }
}

extern "C" void kernel_launch(void* const* d_in, const int* in_sizes, int n_in,
                              void* d_out, int out_size) {
    const float* x  = (const float*)d_in[0];   // (64, 64, 32, 32) fp32
    const float* cb = (const float*)d_in[1];   // (512, 64) fp32
    float* out = (float*)d_out;

    cudaFuncSetAttribute(vq_main, cudaFuncAttributeMaxDynamicSharedMemorySize,
                         SMEM_SZ);

    vq_main<<<GRID, THREADS, SMEM_SZ>>>(x, cb);
    combine_kernel<<<NPIX / 256, 256>>>(cb, out);
}